// round 4
// baseline (speedup 1.0000x reference)
#include <cuda_runtime.h>
#include <cuda_bf16.h>

// Fixed problem shapes:
//   tex (8,16,512,512) f32, iuv (8,3,512,512) i32, lut (24,256,256,2) f32,
//   tex_res = 512 (1-element i32 device scalar), out (8,16,512,512) f32.
#define BB 8
#define CC 16
#define RR 512
#define RR2 (RR * RR)        // 2^18
#define HW  (512 * 512)      // 2^18
#define LOG2_RR2 18
#define NB 4                 // batches per chunk -> scratch 64 MiB, L2-resident
#define NCHUNK (BB / NB)     // 2

#define TILE_PX 512          // pixels per block in gather
#define SW 516               // smem row pitch in floats (padded, mult of 4)

// Transposed-tex scratch for one chunk: [bl][pixel][channel], 64 MiB.
// Stays L2-resident; all stream-once traffic uses .cs so these lines win.
__device__ float g_scratch[(size_t)NB * RR2 * CC];

// ---------------------------------------------------------------------------
// Transpose chunk: (NB,C,R,R) slice of tex -> scratch (NB,R*R,C).
// One thread = 4 channels of one pixel (float4 write).
// ---------------------------------------------------------------------------
__global__ void __launch_bounds__(256) transpose_kernel(
    const float* __restrict__ tex, int b0)
{
    int idx = blockIdx.x * blockDim.x + threadIdx.x;   // [0, NB*RR2*4)
    int c4 = idx & 3;
    int p  = (idx >> 2) & (RR2 - 1);
    int bl = idx >> (2 + LOG2_RR2);
    int b  = b0 + bl;

    const float* src = tex + ((size_t)b * CC + (size_t)c4 * 4) * RR2 + p;
    float4 v;
    v.x = __ldcs(src + 0 * RR2);
    v.y = __ldcs(src + 1 * RR2);
    v.z = __ldcs(src + 2 * RR2);
    v.w = __ldcs(src + 3 * RR2);
    reinterpret_cast<float4*>(g_scratch)[idx] = v;
}

// ---------------------------------------------------------------------------
// Gather: block = 256 threads handles TILE_PX=512 consecutive pixels.
// Phase 1: 4 lanes cooperate on one pixel (lane c4 loads channels 4c4..4c4+3),
//          so a warp's gather LDG.128 touches only ~8 distinct lines instead
//          of 32 -> ~4x fewer L1 wavefronts. Results staged in smem
//          channel-major.
// Phase 2: coalesced float4 stores to out (B,C,H,W).
// ---------------------------------------------------------------------------
__global__ void __launch_bounds__(256) densepose_kernel(
    const int*   __restrict__ iuv,
    const float* __restrict__ lut,
    const int*   __restrict__ tex_res_ptr,
    float*       __restrict__ out, int b0)
{
    __shared__ float s[CC * SW];           // 16 x 516 floats = 33 KB

    int t = threadIdx.x;
    int c4 = t & 3;
    int gpx0 = blockIdx.x * TILE_PX;       // tile start in [0, NB*RR2)
    int bl   = gpx0 >> LOG2_RR2;           // local batch (constant per block)
    int pix0 = gpx0 & (RR2 - 1);           // tile start within batch image
    int b    = b0 + bl;

    const int*   iuvb = iuv + (size_t)b * 3 * HW + pix0;
    const float* scr  = g_scratch + (size_t)bl * RR2 * CC;
    float resm1 = (float)(__ldg(tex_res_ptr) - 1);

    // Phase 1: 8 passes x 64 pixels. Passes are independent -> high MLP.
    #pragma unroll
    for (int pass = 0; pass < 8; pass++) {
        int pxl = pass * 64 + (t >> 2);    // pixel within tile [0,512)

        int part = __ldcs(iuvb + pxl);
        int u8   = __ldcs(iuvb + 1 * HW + pxl);
        int v8   = __ldcs(iuvb + 2 * HW + pxl);

        int i = min(max(part - 1, 0), 23);
        // Replicate reference float math exactly (rn = half-to-even).
        float uf = fminf(fmaxf((float)u8 * (1.0f / 255.0f), 0.0f), 1.0f);
        float vf = fminf(fmaxf((float)v8 * (1.0f / 255.0f), 0.0f), 1.0f);
        int ui = __float2int_rn(uf * 255.0f);
        int vi = __float2int_rn(vf * 255.0f);

        float2 uv = __ldg(reinterpret_cast<const float2*>(lut)
                          + ((size_t)i * 256 + vi) * 256 + ui);

        int u_I = min(max(__float2int_rn(uv.x * resm1), 0), RR - 1);
        int v_I = min(max(__float2int_rn((1.0f - uv.y) * resm1), 0), RR - 1);

        // Lane c4 loads channels [4*c4, 4*c4+4) of this pixel: the 4 lanes
        // of one pixel share a 64B range -> warp gather = ~8 lines.
        float4 g = __ldg(reinterpret_cast<const float4*>(scr)
                         + ((size_t)v_I * RR + u_I) * 4 + c4);
        if (part <= 0) g = make_float4(0.f, 0.f, 0.f, 0.f);

        int cb = c4 * 4;
        s[(cb + 0) * SW + pxl] = g.x;
        s[(cb + 1) * SW + pxl] = g.y;
        s[(cb + 2) * SW + pxl] = g.z;
        s[(cb + 3) * SW + pxl] = g.w;
    }

    __syncthreads();

    // Phase 2: coalesced stores. thread -> channel c = t>>4, px chunk (t&15)*4.
    int c   = t >> 4;                      // 0..15
    int pxo = (t & 15) * 4;                // 0,4,...,60
    float* ob = out + ((size_t)b * CC + c) * HW + pix0;
    #pragma unroll
    for (int iter = 0; iter < 8; iter++) {
        int px = pxo + iter * 64;
        float4 v = *reinterpret_cast<const float4*>(&s[c * SW + px]);
        __stcs(reinterpret_cast<float4*>(ob + px), v);
    }
}

extern "C" void kernel_launch(void* const* d_in, const int* in_sizes, int n_in,
                              void* d_out, int out_size)
{
    const float* tex     = (const float*)d_in[0];
    const int*   iuv     = (const int*)  d_in[1];
    const float* lut     = (const float*)d_in[2];
    const int*   tex_res = (const int*)  d_in[3];
    float* out = (float*)d_out;

    for (int k = 0; k < NCHUNK; k++) {
        int b0 = k * NB;
        transpose_kernel<<<(NB * RR2 * 4) / 256, 256>>>(tex, b0);
        densepose_kernel<<<(NB * RR2) / TILE_PX, 256>>>(iuv, lut, tex_res,
                                                        out, b0);
    }
}

// round 5
// speedup vs baseline: 1.0387x; 1.0387x over previous
#include <cuda_runtime.h>
#include <cuda_bf16.h>

// Fixed problem shapes:
//   tex (8,16,512,512) f32, iuv (8,3,512,512) i32, lut (24,256,256,2) f32,
//   tex_res = 512 (1-element i32 device scalar), out (8,16,512,512) f32.
#define BB 8
#define CC 16
#define RR 512
#define RR2 (RR * RR)        // 2^18
#define HW  (512 * 512)      // 2^18
#define CHUNK_ELEMS ((size_t)RR2 * CC)   // one batch transposed: 16 MiB

// Double-buffered transposed-tex scratch: [buf][pixel][channel].
// 2 x 16 MiB = 32 MiB total (same L2 footprint as the best round) —
// stays L2-resident since all stream-once traffic uses .cs (evict-first).
__device__ float g_scratch[2 * CHUNK_ELEMS];

// ---------------------------------------------------------------------------
// Transpose one batch: (C,R,R) -> scratch (R*R,C).
// One thread = 4 channels of one pixel (float4 write, fully coalesced).
// ---------------------------------------------------------------------------
__global__ void __launch_bounds__(256) transpose_kernel(
    const float* __restrict__ tex, int b, int buf)
{
    int idx = blockIdx.x * blockDim.x + threadIdx.x;   // [0, RR2*4)
    int c4 = idx & 3;                                   // channel group
    int p  = idx >> 2;                                  // pixel

    const float* src = tex + ((size_t)b * CC + (size_t)c4 * 4) * RR2 + p;
    float4 v;
    v.x = __ldcs(src + 0 * RR2);
    v.y = __ldcs(src + 1 * RR2);
    v.z = __ldcs(src + 2 * RR2);
    v.w = __ldcs(src + 3 * RR2);
    reinterpret_cast<float4*>(g_scratch + (size_t)buf * CHUNK_ELEMS)[idx] = v;
}

// ---------------------------------------------------------------------------
// Gather one batch: one thread per pixel; 16 channels = 64 contiguous bytes
// from the L2-hot scratch (4 x LDG.128). R2-proven shape: 25 regs, occ ~80%.
// ---------------------------------------------------------------------------
__global__ void __launch_bounds__(256) densepose_kernel(
    const int*   __restrict__ iuv,
    const float* __restrict__ lut,
    const int*   __restrict__ tex_res_ptr,
    float*       __restrict__ out, int b, int buf)
{
    int pix = blockIdx.x * blockDim.x + threadIdx.x;   // [0, HW)

    const int* iuvb = iuv + (size_t)b * 3 * HW + pix;
    int part = __ldcs(iuvb);

    float4 r0 = make_float4(0.f, 0.f, 0.f, 0.f);
    float4 r1 = r0, r2 = r0, r3 = r0;

    if (part > 0) {
        int u8 = __ldcs(iuvb + 1 * HW);
        int v8 = __ldcs(iuvb + 2 * HW);

        int i = min(max(part - 1, 0), 23);

        // Replicate reference float math exactly (rn = half-to-even).
        float uf = fminf(fmaxf((float)u8 * (1.0f / 255.0f), 0.0f), 1.0f);
        float vf = fminf(fmaxf((float)v8 * (1.0f / 255.0f), 0.0f), 1.0f);
        int ui = __float2int_rn(uf * 255.0f);
        int vi = __float2int_rn(vf * 255.0f);

        float2 uv = __ldg(reinterpret_cast<const float2*>(lut)
                          + ((size_t)i * 256 + vi) * 256 + ui);

        float resm1 = (float)(__ldg(tex_res_ptr) - 1);
        int u_I = min(max(__float2int_rn(uv.x * resm1), 0), RR - 1);
        int v_I = min(max(__float2int_rn((1.0f - uv.y) * resm1), 0), RR - 1);

        const float4* src = reinterpret_cast<const float4*>(
                                g_scratch + (size_t)buf * CHUNK_ELEMS)
                          + ((size_t)v_I * RR + u_I) * 4;
        r0 = __ldg(src + 0);
        r1 = __ldg(src + 1);
        r2 = __ldg(src + 2);
        r3 = __ldg(src + 3);
    }

    float* o = out + (size_t)b * CC * HW + pix;
    __stcs(o +  0 * HW, r0.x);  __stcs(o +  1 * HW, r0.y);
    __stcs(o +  2 * HW, r0.z);  __stcs(o +  3 * HW, r0.w);
    __stcs(o +  4 * HW, r1.x);  __stcs(o +  5 * HW, r1.y);
    __stcs(o +  6 * HW, r1.z);  __stcs(o +  7 * HW, r1.w);
    __stcs(o +  8 * HW, r2.x);  __stcs(o +  9 * HW, r2.y);
    __stcs(o + 10 * HW, r2.z);  __stcs(o + 11 * HW, r2.w);
    __stcs(o + 12 * HW, r3.x);  __stcs(o + 13 * HW, r3.y);
    __stcs(o + 14 * HW, r3.z);  __stcs(o + 15 * HW, r3.w);
}

extern "C" void kernel_launch(void* const* d_in, const int* in_sizes, int n_in,
                              void* d_out, int out_size)
{
    const float* tex     = (const float*)d_in[0];
    const int*   iuv     = (const int*)  d_in[1];
    const float* lut     = (const float*)d_in[2];
    const int*   tex_res = (const int*)  d_in[3];
    float* out = (float*)d_out;

    const int TR_BLOCKS = (RR2 * 4) / 256;   // 4096
    const int DP_BLOCKS = HW / 256;          // 1024

    // Second stream for the transpose pipeline. Fork-join via events so the
    // whole thing is capturable as a branched graph. Fallback: sequential.
    cudaStream_t s2 = 0;
    bool two = (cudaStreamCreateWithFlags(&s2, cudaStreamNonBlocking)
                == cudaSuccess);

    if (!two) {
        for (int b = 0; b < BB; b++) {
            transpose_kernel<<<TR_BLOCKS, 256>>>(tex, b, b & 1);
            densepose_kernel<<<DP_BLOCKS, 256>>>(iuv, lut, tex_res, out,
                                                 b, b & 1);
        }
        return;
    }

    cudaEvent_t eFork, eT[BB], eG[BB];
    cudaEventCreateWithFlags(&eFork, cudaEventDisableTiming);
    for (int k = 0; k < BB; k++) {
        cudaEventCreateWithFlags(&eT[k], cudaEventDisableTiming);
        cudaEventCreateWithFlags(&eG[k], cudaEventDisableTiming);
    }

    // Fork: s2 branches off the main (capture) stream.
    cudaEventRecord(eFork, 0);
    cudaStreamWaitEvent(s2, eFork, 0);

    // Prime the pipeline: T0, T1 on s2.
    transpose_kernel<<<TR_BLOCKS, 256, 0, s2>>>(tex, 0, 0);
    cudaEventRecord(eT[0], s2);
    transpose_kernel<<<TR_BLOCKS, 256, 0, s2>>>(tex, 1, 1);
    cudaEventRecord(eT[1], s2);

    // Steady state: g(k) on stream 0 overlapped with T(k+2) on s2.
    // g(k) waits T(k); T(k+2) waits g(k) (WAR: reuses buffer k&1).
    for (int k = 0; k < BB; k++) {
        cudaStreamWaitEvent(0, eT[k], 0);
        densepose_kernel<<<DP_BLOCKS, 256>>>(iuv, lut, tex_res, out, k, k & 1);
        if (k + 2 < BB) {
            cudaEventRecord(eG[k], 0);
            cudaStreamWaitEvent(s2, eG[k], 0);
            transpose_kernel<<<TR_BLOCKS, 256, 0, s2>>>(tex, k + 2, k & 1);
            cudaEventRecord(eT[k + 2], s2);
        }
    }
    // Join: the last gather g(BB-1) already waits eT[BB-1], s2's final node,
    // so the graph re-converges on the main stream.

    // Clean up host objects only when not capturing (destroying a stream
    // that participated in an active capture would invalidate it).
    cudaStreamCaptureStatus st = cudaStreamCaptureStatusNone;
    cudaStreamIsCapturing(0, &st);
    if (st == cudaStreamCaptureStatusNone) {
        cudaStreamDestroy(s2);
        cudaEventDestroy(eFork);
        for (int k = 0; k < BB; k++) {
            cudaEventDestroy(eT[k]);
            cudaEventDestroy(eG[k]);
        }
    }
}